// round 10
// baseline (speedup 1.0000x reference)
#include <cuda_runtime.h>

#define N_NODES 500000
#define N_EDGES 16000000
#define NB_BLK  ((N_NODES + 255) / 256)   // 1954 degree-scan blocks

// ---------------- scratch (device globals; no allocs allowed) ----------------
__device__ int       g_src[N_EDGES];        // 64 MB (decoded src, int64 input only)
__device__ int       g_dst[N_EDGES];        // 64 MB (decoded dst, int64 input only)
__device__ int       g_csr_src[N_EDGES];    // 64 MB (CSR-by-dst adjacency)
__device__ unsigned  g_deg[N_NODES];        // 2 MB  (edge-only in-degree)
__device__ unsigned  g_excl[N_NODES];       // 2 MB  (block-local exclusive prefix)
__device__ unsigned  g_bsum[NB_BLK];        //       (per-block degree sums)
__device__ unsigned  g_boff[NB_BLK];        //       (exclusive block offsets)
__device__ unsigned  g_row_start[N_NODES + 1];
__device__ unsigned  g_cursor[N_NODES];     // 2 MB  (scatter cursors)
__device__ float     g_dinv[N_NODES];       // 2 MB
__device__ float4    g_xw[N_NODES];         // 8 MB  (pre-scaled xw*dinv, 4-wide layers)
__device__ float4    g_agg[N_NODES];        // 8 MB
__device__ float2    g_xw2[N_NODES];        // 4 MB  (layer-3 pre-scaled)
__device__ int       g_is64;

// ---------------- layout detection (int32 vs int64 edge_index) ----------------
__global__ void k_detect(const int* __restrict__ e) {
    __shared__ int nz;
    if (threadIdx.x == 0) nz = 0;
    __syncthreads();
    int local = 0;
    #pragma unroll
    for (int m = 0; m < 16; m++) {
        int k = (int)((((unsigned)threadIdx.x * 16u + m) * 7919u) & (16u * 1024u * 1024u - 1u));
        if (e[2 * k + 1] != 0) local = 1;
    }
    if (local) atomicOr(&nz, 1);
    __syncthreads();
    if (threadIdx.x == 0) g_is64 = (nz == 0) ? 1 : 0;
}

__global__ void k_zero_deg() {
    int i = blockIdx.x * blockDim.x + threadIdx.x;
    if (i < N_NODES) g_deg[i] = 0u;
}

// Degree histogram (+ int64 -> int32 decode into scratch when needed).
__global__ void k_prep_edges(const int* __restrict__ e) {
    int t = blockIdx.x * blockDim.x + threadIdx.x;   // edges 4t..4t+3
    if (4 * t >= N_EDGES) return;
    int4 d;
    if (g_is64) {
        const int4* e4 = (const int4*)e;
        int4 a = e4[2 * t];
        int4 b = e4[2 * t + 1];
        int4 c = e4[(N_EDGES / 2) + 2 * t];
        int4 f = e4[(N_EDGES / 2) + 2 * t + 1];
        ((int4*)g_src)[t] = make_int4(a.x, a.z, b.x, b.z);
        d = make_int4(c.x, c.z, f.x, f.z);
        ((int4*)g_dst)[t] = d;
    } else {
        d = ((const int4*)e)[(N_EDGES / 4) + t];
    }
    atomicAdd(&g_deg[d.x], 1u);
    atomicAdd(&g_deg[d.y], 1u);
    atomicAdd(&g_deg[d.z], 1u);
    atomicAdd(&g_deg[d.w], 1u);
}

// ---------------- prefix sum: block scan + block-sum scan + combine ----------
__global__ void k_bsum() {   // grid NB_BLK, block 256
    __shared__ unsigned sh[256];
    int tid = threadIdx.x;
    int i = blockIdx.x * 256 + tid;
    unsigned v = (i < N_NODES) ? g_deg[i] : 0u;
    sh[tid] = v;
    __syncthreads();
    for (int off = 1; off < 256; off <<= 1) {
        unsigned t = (tid >= off) ? sh[tid - off] : 0u;
        __syncthreads();
        sh[tid] += t;
        __syncthreads();
    }
    if (i < N_NODES) g_excl[i] = sh[tid] - v;       // exclusive within block
    if (tid == 255) g_bsum[blockIdx.x] = sh[255];   // block total
}

__global__ void k_scan_bsum() {  // 1 block, 1024 threads, NB_BLK <= 2048
    __shared__ unsigned sh[1024];
    int t = threadIdx.x;
    unsigned a0 = (2 * t     < NB_BLK) ? g_bsum[2 * t]     : 0u;
    unsigned a1 = (2 * t + 1 < NB_BLK) ? g_bsum[2 * t + 1] : 0u;
    unsigned s = a0 + a1;
    sh[t] = s;
    __syncthreads();
    for (int off = 1; off < 1024; off <<= 1) {
        unsigned v = (t >= off) ? sh[t - off] : 0u;
        __syncthreads();
        sh[t] += v;
        __syncthreads();
    }
    unsigned excl = sh[t] - s;
    if (2 * t     < NB_BLK) g_boff[2 * t]     = excl;
    if (2 * t + 1 < NB_BLK) g_boff[2 * t + 1] = excl + a0;
}

// row_start = excl + block offset; init scatter cursor; compute dinv. One pass.
__global__ void k_row_start() {
    int i = blockIdx.x * blockDim.x + threadIdx.x;
    if (i >= N_NODES) return;
    unsigned r = g_excl[i] + g_boff[i >> 8];
    g_row_start[i] = r;
    g_cursor[i]    = r;
    g_dinv[i]      = rsqrtf((float)g_deg[i] + 1.0f);
    if (i == 0) g_row_start[N_NODES] = N_EDGES;
}

// Counting-sort scatter: csr_src[cursor[dst]++] = src.
__global__ void k_scatter(const int* __restrict__ e) {
    int t = blockIdx.x * blockDim.x + threadIdx.x;
    if (4 * t >= N_EDGES) return;
    int4 s, d;
    if (g_is64) {
        s = ((const int4*)g_src)[t];
        d = ((const int4*)g_dst)[t];
    } else {
        s = ((const int4*)e)[t];
        d = ((const int4*)e)[(N_EDGES / 4) + t];
    }
    g_csr_src[atomicAdd(&g_cursor[d.x], 1u)] = s.x;
    g_csr_src[atomicAdd(&g_cursor[d.y], 1u)] = s.y;
    g_csr_src[atomicAdd(&g_cursor[d.z], 1u)] = s.z;
    g_csr_src[atomicAdd(&g_cursor[d.w], 1u)] = s.w;
}

// ---------------- node stages (unchanged algebra) ----------------
__global__ void k_node1(const float* __restrict__ x, const float* __restrict__ W1) {
    int i = blockIdx.x * blockDim.x + threadIdx.x;
    if (i >= N_NODES) return;
    float2 xi = ((const float2*)x)[i];
    float di = g_dinv[i];
    float4 r;
    r.x = (xi.x * W1[0] + xi.y * W1[4]) * di;
    r.y = (xi.x * W1[1] + xi.y * W1[5]) * di;
    r.z = (xi.x * W1[2] + xi.y * W1[6]) * di;
    r.w = (xi.x * W1[3] + xi.y * W1[7]) * di;
    g_xw[i] = r;
}

__global__ void k_node2(const float* __restrict__ W2, const float* __restrict__ b1) {
    int i = blockIdx.x * blockDim.x + threadIdx.x;
    if (i >= N_NODES) return;
    float di = g_dinv[i];
    float4 a = g_agg[i];
    float hx = tanhf(a.x * di + b1[0]);
    float hy = tanhf(a.y * di + b1[1]);
    float hz = tanhf(a.z * di + b1[2]);
    float hw = tanhf(a.w * di + b1[3]);
    float4 r;
    r.x = (hx * W2[0] + hy * W2[4] + hz * W2[8]  + hw * W2[12]) * di;
    r.y = (hx * W2[1] + hy * W2[5] + hz * W2[9]  + hw * W2[13]) * di;
    r.z = (hx * W2[2] + hy * W2[6] + hz * W2[10] + hw * W2[14]) * di;
    r.w = (hx * W2[3] + hy * W2[7] + hz * W2[11] + hw * W2[15]) * di;
    g_xw[i] = r;
}

__global__ void k_node3(const float* __restrict__ W3, const float* __restrict__ b2) {
    int i = blockIdx.x * blockDim.x + threadIdx.x;
    if (i >= N_NODES) return;
    float di = g_dinv[i];
    float4 a = g_agg[i];
    float hx = tanhf(a.x * di + b2[0]);
    float hy = tanhf(a.y * di + b2[1]);
    float hz = tanhf(a.z * di + b2[2]);
    float hw = tanhf(a.w * di + b2[3]);
    float2 r;
    r.x = (hx * W3[0] + hy * W3[2] + hz * W3[4] + hw * W3[6]) * di;
    r.y = (hx * W3[1] + hy * W3[3] + hz * W3[5] + hw * W3[7]) * di;
    g_xw2[i] = r;
}

// ---------------- CSR pull aggregation: warp per node, no atomics ------------
__global__ void k_gather4() {
    int gt = blockIdx.x * blockDim.x + threadIdx.x;
    int node = gt >> 5;
    int lane = gt & 31;
    if (node >= N_NODES) return;
    unsigned start = g_row_start[node], end = g_row_start[node + 1];
    float4 acc = make_float4(0.f, 0.f, 0.f, 0.f);
    for (unsigned j = start + lane; j < end; j += 32) {
        float4 v = g_xw[g_csr_src[j]];
        acc.x += v.x; acc.y += v.y; acc.z += v.z; acc.w += v.w;
    }
    #pragma unroll
    for (int o = 16; o > 0; o >>= 1) {
        acc.x += __shfl_xor_sync(0xFFFFFFFFu, acc.x, o);
        acc.y += __shfl_xor_sync(0xFFFFFFFFu, acc.y, o);
        acc.z += __shfl_xor_sync(0xFFFFFFFFu, acc.z, o);
        acc.w += __shfl_xor_sync(0xFFFFFFFFu, acc.w, o);
    }
    if (lane == 0) {
        float4 self = g_xw[node];   // self-loop term (pre-scaled)
        g_agg[node] = make_float4(self.x + acc.x, self.y + acc.y,
                                  self.z + acc.z, self.w + acc.w);
    }
}

// Final layer: gather 2-wide, fuse dinv scale + bias into lane-0 write.
__global__ void k_gather2(float2* __restrict__ out, const float* __restrict__ b3) {
    int gt = blockIdx.x * blockDim.x + threadIdx.x;
    int node = gt >> 5;
    int lane = gt & 31;
    if (node >= N_NODES) return;
    unsigned start = g_row_start[node], end = g_row_start[node + 1];
    float2 acc = make_float2(0.f, 0.f);
    for (unsigned j = start + lane; j < end; j += 32) {
        float2 v = g_xw2[g_csr_src[j]];
        acc.x += v.x; acc.y += v.y;
    }
    #pragma unroll
    for (int o = 16; o > 0; o >>= 1) {
        acc.x += __shfl_xor_sync(0xFFFFFFFFu, acc.x, o);
        acc.y += __shfl_xor_sync(0xFFFFFFFFu, acc.y, o);
    }
    if (lane == 0) {
        float2 self = g_xw2[node];
        float di = g_dinv[node];
        out[node] = make_float2((self.x + acc.x) * di + b3[0],
                                (self.y + acc.y) * di + b3[1]);
    }
}

// ---------------- launch ----------------
extern "C" void kernel_launch(void* const* d_in, const int* in_sizes, int n_in,
                              void* d_out, int out_size) {
    const float* x  = (const float*)d_in[0];
    const int*   e  = (const int*)d_in[1];
    const float* W1 = (const float*)d_in[2];
    const float* b1 = (const float*)d_in[3];
    const float* W2 = (const float*)d_in[4];
    const float* b2 = (const float*)d_in[5];
    const float* W3 = (const float*)d_in[6];
    const float* b3 = (const float*)d_in[7];
    float2* out = (float2*)d_out;

    const int TB = 256;
    const int gNode   = (N_NODES + TB - 1) / TB;
    const int gEdge4  = (N_EDGES / 4 + TB - 1) / TB;
    const int gGather = (N_NODES * 32 + TB - 1) / TB;   // warp per node

    k_detect<<<1, 256>>>(e);
    k_zero_deg<<<gNode, TB>>>();
    k_prep_edges<<<gEdge4, TB>>>(e);

    k_bsum<<<NB_BLK, 256>>>();
    k_scan_bsum<<<1, 1024>>>();
    k_row_start<<<gNode, TB>>>();
    k_scatter<<<gEdge4, TB>>>(e);

    k_node1<<<gNode, TB>>>(x, W1);
    k_gather4<<<gGather, TB>>>();

    k_node2<<<gNode, TB>>>(W2, b1);
    k_gather4<<<gGather, TB>>>();

    k_node3<<<gNode, TB>>>(W3, b2);
    k_gather2<<<gGather, TB>>>(out, b3);
}

// round 11
// speedup vs baseline: 1.3384x; 1.3384x over previous
#include <cuda_runtime.h>

#define N_NODES 500000
#define N_EDGES 16000000

// ---------------- scratch (device globals; no allocs allowed) ----------------
__device__ int       g_src[N_EDGES];     // 64 MB (decoded src, int64 input only)
__device__ int       g_dst[N_EDGES];     // 64 MB (decoded dst, int64 input only)
__device__ unsigned  g_deg[N_NODES];     // 2 MB
__device__ float     g_dinv[N_NODES];    // 2 MB
__device__ float4    g_xw[N_NODES];      // 8 MB  (pre-scaled xw*dinv, 4-wide layers)
__device__ float4    g_agg[N_NODES];     // 8 MB  (accumulator, init = self term)
__device__ float2    g_xw2[N_NODES];     // 4 MB  (layer-3 pre-scaled)
__device__ int       g_is64;             // edge dtype flag

// ---------------- vector red helpers ----------------
__device__ __forceinline__ void red_add_f4(float4* p, float4 v) {
    asm volatile("red.global.add.v4.f32 [%0], {%1,%2,%3,%4};"
                 :: "l"(p), "f"(v.x), "f"(v.y), "f"(v.z), "f"(v.w) : "memory");
}
__device__ __forceinline__ void red_add_f2(float2* p, float2 v) {
    asm volatile("red.global.add.v2.f32 [%0], {%1,%2};"
                 :: "l"(p), "f"(v.x), "f"(v.y) : "memory");
}

// ---------------- layout detection (int32 vs int64 edge_index) ----------------
__global__ void k_detect(const int* __restrict__ e) {
    __shared__ int nz;
    if (threadIdx.x == 0) nz = 0;
    __syncthreads();
    int local = 0;
    #pragma unroll
    for (int m = 0; m < 16; m++) {
        int k = (int)((((unsigned)threadIdx.x * 16u + m) * 7919u) & (16u * 1024u * 1024u - 1u));
        if (e[2 * k + 1] != 0) local = 1;
    }
    if (local) atomicOr(&nz, 1);
    __syncthreads();
    if (threadIdx.x == 0) g_is64 = (nz == 0) ? 1 : 0;
}

__global__ void k_zero_deg() {
    int i = blockIdx.x * blockDim.x + threadIdx.x;
    if (i < N_NODES) g_deg[i] = 0u;
}

// Degree histogram (+ int64 -> int32 decode into scratch when needed).
// Index loads are streaming (.cs) — never let the stream evict hot tables.
__global__ void k_prep_edges(const int* __restrict__ e) {
    int t = blockIdx.x * blockDim.x + threadIdx.x;   // edges 4t..4t+3
    if (4 * t >= N_EDGES) return;
    int4 d;
    if (g_is64) {
        const int4* e4 = (const int4*)e;
        int4 a = __ldcs(&e4[2 * t]);
        int4 b = __ldcs(&e4[2 * t + 1]);
        int4 c = __ldcs(&e4[(N_EDGES / 2) + 2 * t]);
        int4 f = __ldcs(&e4[(N_EDGES / 2) + 2 * t + 1]);
        ((int4*)g_src)[t] = make_int4(a.x, a.z, b.x, b.z);
        d = make_int4(c.x, c.z, f.x, f.z);
        ((int4*)g_dst)[t] = d;
    } else {
        d = __ldcs(&((const int4*)e)[(N_EDGES / 4) + t]);
    }
    atomicAdd(&g_deg[d.x], 1u);
    atomicAdd(&g_deg[d.y], 1u);
    atomicAdd(&g_deg[d.z], 1u);
    atomicAdd(&g_deg[d.w], 1u);
}

// Layer 1 node stage (dinv fused): di = rsqrt(deg+1); xws = (x@W1)*di;
// agg init = self term.
__global__ void k_node1(const float* __restrict__ x, const float* __restrict__ W1) {
    int i = blockIdx.x * blockDim.x + threadIdx.x;
    if (i >= N_NODES) return;
    float di = rsqrtf((float)g_deg[i] + 1.0f);
    g_dinv[i] = di;
    float2 xi = ((const float2*)x)[i];
    float4 r;
    r.x = (xi.x * W1[0] + xi.y * W1[4]) * di;
    r.y = (xi.x * W1[1] + xi.y * W1[5]) * di;
    r.z = (xi.x * W1[2] + xi.y * W1[6]) * di;
    r.w = (xi.x * W1[3] + xi.y * W1[7]) * di;
    g_xw[i]  = r;
    g_agg[i] = r;
}

// Edge pass, 4-wide layers: agg[dst] += xws[src]. 8 edges/thread for MLP;
// streaming index loads keep g_xw/g_agg resident in L2.
__global__ void k_edge4(const int* __restrict__ e) {
    int t = blockIdx.x * blockDim.x + threadIdx.x;   // edges 8t..8t+7
    if (8 * t >= N_EDGES) return;
    int4 s0, s1, d0, d1;
    if (g_is64) {
        const int4* sp = (const int4*)g_src;
        const int4* dp = (const int4*)g_dst;
        s0 = __ldcs(&sp[2 * t]);     s1 = __ldcs(&sp[2 * t + 1]);
        d0 = __ldcs(&dp[2 * t]);     d1 = __ldcs(&dp[2 * t + 1]);
    } else {
        const int4* e4 = (const int4*)e;
        s0 = __ldcs(&e4[2 * t]);     s1 = __ldcs(&e4[2 * t + 1]);
        d0 = __ldcs(&e4[(N_EDGES / 4) + 2 * t]);
        d1 = __ldcs(&e4[(N_EDGES / 4) + 2 * t + 1]);
    }
    // 8 independent gathers (high MLP), then 8 fire-and-forget reds
    float4 v0 = g_xw[s0.x];
    float4 v1 = g_xw[s0.y];
    float4 v2 = g_xw[s0.z];
    float4 v3 = g_xw[s0.w];
    float4 v4 = g_xw[s1.x];
    float4 v5 = g_xw[s1.y];
    float4 v6 = g_xw[s1.z];
    float4 v7 = g_xw[s1.w];
    red_add_f4(&g_agg[d0.x], v0);
    red_add_f4(&g_agg[d0.y], v1);
    red_add_f4(&g_agg[d0.z], v2);
    red_add_f4(&g_agg[d0.w], v3);
    red_add_f4(&g_agg[d1.x], v4);
    red_add_f4(&g_agg[d1.y], v5);
    red_add_f4(&g_agg[d1.z], v6);
    red_add_f4(&g_agg[d1.w], v7);
}

// Layer 2 node stage: h = tanh(agg*dinv + b1); xws2 = (h@W2)*dinv; re-init agg.
__global__ void k_node2(const float* __restrict__ W2, const float* __restrict__ b1) {
    int i = blockIdx.x * blockDim.x + threadIdx.x;
    if (i >= N_NODES) return;
    float di = g_dinv[i];
    float4 a = g_agg[i];
    float hx = tanhf(a.x * di + b1[0]);
    float hy = tanhf(a.y * di + b1[1]);
    float hz = tanhf(a.z * di + b1[2]);
    float hw = tanhf(a.w * di + b1[3]);
    float4 r;
    r.x = (hx * W2[0] + hy * W2[4] + hz * W2[8]  + hw * W2[12]) * di;
    r.y = (hx * W2[1] + hy * W2[5] + hz * W2[9]  + hw * W2[13]) * di;
    r.z = (hx * W2[2] + hy * W2[6] + hz * W2[10] + hw * W2[14]) * di;
    r.w = (hx * W2[3] + hy * W2[7] + hz * W2[11] + hw * W2[15]) * di;
    g_xw[i]  = r;
    g_agg[i] = r;
}

// Layer 3 node stage: h = tanh(agg*dinv + b2); xws3 = (h@W3)*dinv (2-wide);
// out initialized with self term (out is the layer-3 accumulator).
__global__ void k_node3(const float* __restrict__ W3, const float* __restrict__ b2,
                        float2* __restrict__ out) {
    int i = blockIdx.x * blockDim.x + threadIdx.x;
    if (i >= N_NODES) return;
    float di = g_dinv[i];
    float4 a = g_agg[i];
    float hx = tanhf(a.x * di + b2[0]);
    float hy = tanhf(a.y * di + b2[1]);
    float hz = tanhf(a.z * di + b2[2]);
    float hw = tanhf(a.w * di + b2[3]);
    float2 r;
    r.x = (hx * W3[0] + hy * W3[2] + hz * W3[4] + hw * W3[6]) * di;
    r.y = (hx * W3[1] + hy * W3[3] + hz * W3[5] + hw * W3[7]) * di;
    g_xw2[i] = r;
    out[i]   = r;
}

// Edge pass, 2-wide final layer, accumulating straight into d_out.
__global__ void k_edge2(const int* __restrict__ e, float2* __restrict__ out) {
    int t = blockIdx.x * blockDim.x + threadIdx.x;   // edges 8t..8t+7
    if (8 * t >= N_EDGES) return;
    int4 s0, s1, d0, d1;
    if (g_is64) {
        const int4* sp = (const int4*)g_src;
        const int4* dp = (const int4*)g_dst;
        s0 = __ldcs(&sp[2 * t]);     s1 = __ldcs(&sp[2 * t + 1]);
        d0 = __ldcs(&dp[2 * t]);     d1 = __ldcs(&dp[2 * t + 1]);
    } else {
        const int4* e4 = (const int4*)e;
        s0 = __ldcs(&e4[2 * t]);     s1 = __ldcs(&e4[2 * t + 1]);
        d0 = __ldcs(&e4[(N_EDGES / 4) + 2 * t]);
        d1 = __ldcs(&e4[(N_EDGES / 4) + 2 * t + 1]);
    }
    float2 v0 = g_xw2[s0.x];
    float2 v1 = g_xw2[s0.y];
    float2 v2 = g_xw2[s0.z];
    float2 v3 = g_xw2[s0.w];
    float2 v4 = g_xw2[s1.x];
    float2 v5 = g_xw2[s1.y];
    float2 v6 = g_xw2[s1.z];
    float2 v7 = g_xw2[s1.w];
    red_add_f2(&out[d0.x], v0);
    red_add_f2(&out[d0.y], v1);
    red_add_f2(&out[d0.z], v2);
    red_add_f2(&out[d0.w], v3);
    red_add_f2(&out[d1.x], v4);
    red_add_f2(&out[d1.y], v5);
    red_add_f2(&out[d1.z], v6);
    red_add_f2(&out[d1.w], v7);
}

// Final scale + bias: out_i = agg_i * dinv_i + b3 (no tanh on last layer).
__global__ void k_finalize(float2* __restrict__ out, const float* __restrict__ b3) {
    int i = blockIdx.x * blockDim.x + threadIdx.x;
    if (i >= N_NODES) return;
    float di = g_dinv[i];
    float2 a = out[i];
    a.x = a.x * di + b3[0];
    a.y = a.y * di + b3[1];
    out[i] = a;
}

// ---------------- launch ----------------
extern "C" void kernel_launch(void* const* d_in, const int* in_sizes, int n_in,
                              void* d_out, int out_size) {
    const float* x  = (const float*)d_in[0];
    const int*   e  = (const int*)d_in[1];
    const float* W1 = (const float*)d_in[2];
    const float* b1 = (const float*)d_in[3];
    const float* W2 = (const float*)d_in[4];
    const float* b2 = (const float*)d_in[5];
    const float* W3 = (const float*)d_in[6];
    const float* b3 = (const float*)d_in[7];
    float2* out = (float2*)d_out;

    const int TB = 256;
    const int gNode  = (N_NODES + TB - 1) / TB;
    const int gEdge4 = (N_EDGES / 4 + TB - 1) / TB;
    const int gEdge8 = (N_EDGES / 8 + TB - 1) / TB;

    k_detect<<<1, 256>>>(e);
    k_zero_deg<<<gNode, TB>>>();
    k_prep_edges<<<gEdge4, TB>>>(e);

    k_node1<<<gNode, TB>>>(x, W1);
    k_edge4<<<gEdge8, TB>>>(e);

    k_node2<<<gNode, TB>>>(W2, b1);
    k_edge4<<<gEdge8, TB>>>(e);

    k_node3<<<gNode, TB>>>(W3, b2, out);
    k_edge2<<<gEdge8, TB>>>(e, out);
    k_finalize<<<gNode, TB>>>(out, b3);
}

// round 12
// speedup vs baseline: 1.3464x; 1.0060x over previous
#include <cuda_runtime.h>

#define N_NODES 500000
#define N_EDGES 16000000

// ---------------- scratch (device globals; no allocs allowed) ----------------
__device__ int       g_src[N_EDGES];     // 64 MB (decoded src, int64 input only)
__device__ int       g_dst[N_EDGES];     // 64 MB (decoded dst, int64 input only)
__device__ unsigned  g_deg[N_NODES];     // 2 MB
__device__ float     g_dinv[N_NODES];    // 2 MB
__device__ float2    g_xs[N_NODES];      // 4 MB  (layer-1: prescaled raw features x*dinv)
__device__ float2    g_agg2[N_NODES];    // 4 MB  (layer-1 accumulator, 2-wide)
__device__ float4    g_xw[N_NODES];      // 8 MB  (layer-2 prescaled xws)
__device__ float4    g_agg[N_NODES];     // 8 MB  (layer-2 accumulator)
__device__ float2    g_xw2[N_NODES];     // 4 MB  (layer-3 prescaled)
__device__ int       g_is64;             // edge dtype flag

// ---------------- vector red helpers ----------------
__device__ __forceinline__ void red_add_f4(float4* p, float4 v) {
    asm volatile("red.global.add.v4.f32 [%0], {%1,%2,%3,%4};"
                 :: "l"(p), "f"(v.x), "f"(v.y), "f"(v.z), "f"(v.w) : "memory");
}
__device__ __forceinline__ void red_add_f2(float2* p, float2 v) {
    asm volatile("red.global.add.v2.f32 [%0], {%1,%2};"
                 :: "l"(p), "f"(v.x), "f"(v.y) : "memory");
}

// ---------------- layout detection (int32 vs int64 edge_index) ----------------
__global__ void k_detect(const int* __restrict__ e) {
    __shared__ int nz;
    if (threadIdx.x == 0) nz = 0;
    __syncthreads();
    int local = 0;
    #pragma unroll
    for (int m = 0; m < 16; m++) {
        int k = (int)((((unsigned)threadIdx.x * 16u + m) * 7919u) & (16u * 1024u * 1024u - 1u));
        if (e[2 * k + 1] != 0) local = 1;
    }
    if (local) atomicOr(&nz, 1);
    __syncthreads();
    if (threadIdx.x == 0) g_is64 = (nz == 0) ? 1 : 0;
}

__global__ void k_zero_deg() {
    int i = blockIdx.x * blockDim.x + threadIdx.x;
    if (i < N_NODES) g_deg[i] = 0u;
}

// Degree histogram (+ int64 -> int32 decode into scratch when needed).
__global__ void k_prep_edges(const int* __restrict__ e) {
    int t = blockIdx.x * blockDim.x + threadIdx.x;   // edges 4t..4t+3
    if (4 * t >= N_EDGES) return;
    int4 d;
    if (g_is64) {
        const int4* e4 = (const int4*)e;
        int4 a = __ldcs(&e4[2 * t]);
        int4 b = __ldcs(&e4[2 * t + 1]);
        int4 c = __ldcs(&e4[(N_EDGES / 2) + 2 * t]);
        int4 f = __ldcs(&e4[(N_EDGES / 2) + 2 * t + 1]);
        ((int4*)g_src)[t] = make_int4(a.x, a.z, b.x, b.z);
        d = make_int4(c.x, c.z, f.x, f.z);
        ((int4*)g_dst)[t] = d;
    } else {
        d = __ldcs(&((const int4*)e)[(N_EDGES / 4) + t]);
    }
    atomicAdd(&g_deg[d.x], 1u);
    atomicAdd(&g_deg[d.y], 1u);
    atomicAdd(&g_deg[d.z], 1u);
    atomicAdd(&g_deg[d.w], 1u);
}

// Layer-1 node stage: di = rsqrt(deg+1); xs = x*di (RAW 2-wide features,
// W1 deferred past aggregation by linearity); agg2 init = self term.
__global__ void k_node1(const float* __restrict__ x) {
    int i = blockIdx.x * blockDim.x + threadIdx.x;
    if (i >= N_NODES) return;
    float di = rsqrtf((float)g_deg[i] + 1.0f);
    g_dinv[i] = di;
    float2 xi = ((const float2*)x)[i];
    float2 r = make_float2(xi.x * di, xi.y * di);
    g_xs[i]   = r;
    g_agg2[i] = r;
}

// Shared index-fetch for 8-edges/thread passes.
#define LOAD_IDX8(e)                                                     \
    int4 s0, s1, d0, d1;                                                 \
    if (g_is64) {                                                        \
        const int4* sp = (const int4*)g_src;                             \
        const int4* dp = (const int4*)g_dst;                             \
        s0 = __ldcs(&sp[2 * t]);  s1 = __ldcs(&sp[2 * t + 1]);           \
        d0 = __ldcs(&dp[2 * t]);  d1 = __ldcs(&dp[2 * t + 1]);           \
    } else {                                                             \
        const int4* e4 = (const int4*)(e);                               \
        s0 = __ldcs(&e4[2 * t]);  s1 = __ldcs(&e4[2 * t + 1]);           \
        d0 = __ldcs(&e4[(N_EDGES / 4) + 2 * t]);                         \
        d1 = __ldcs(&e4[(N_EDGES / 4) + 2 * t + 1]);                     \
    }

// Layer-1 edge pass: 2-wide. agg2[dst] += xs[src].
__global__ void k_edge1(const int* __restrict__ e) {
    int t = blockIdx.x * blockDim.x + threadIdx.x;
    if (8 * t >= N_EDGES) return;
    LOAD_IDX8(e)
    float2 v0 = g_xs[s0.x];
    float2 v1 = g_xs[s0.y];
    float2 v2 = g_xs[s0.z];
    float2 v3 = g_xs[s0.w];
    float2 v4 = g_xs[s1.x];
    float2 v5 = g_xs[s1.y];
    float2 v6 = g_xs[s1.z];
    float2 v7 = g_xs[s1.w];
    red_add_f2(&g_agg2[d0.x], v0);
    red_add_f2(&g_agg2[d0.y], v1);
    red_add_f2(&g_agg2[d0.z], v2);
    red_add_f2(&g_agg2[d0.w], v3);
    red_add_f2(&g_agg2[d1.x], v4);
    red_add_f2(&g_agg2[d1.y], v5);
    red_add_f2(&g_agg2[d1.z], v6);
    red_add_f2(&g_agg2[d1.w], v7);
}

// Layer-2 node stage: apply deferred W1, bias, tanh; then xws2 = (h@W2)*di.
// pre = (agg2*di) @ W1 + b1   (W1 is [2,4] row-major)
__global__ void k_node2(const float* __restrict__ W1, const float* __restrict__ b1,
                        const float* __restrict__ W2) {
    int i = blockIdx.x * blockDim.x + threadIdx.x;
    if (i >= N_NODES) return;
    float di = g_dinv[i];
    float2 a = g_agg2[i];
    float tx = a.x * di, ty = a.y * di;
    float hx = tanhf(tx * W1[0] + ty * W1[4] + b1[0]);
    float hy = tanhf(tx * W1[1] + ty * W1[5] + b1[1]);
    float hz = tanhf(tx * W1[2] + ty * W1[6] + b1[2]);
    float hw = tanhf(tx * W1[3] + ty * W1[7] + b1[3]);
    float4 r;
    r.x = (hx * W2[0] + hy * W2[4] + hz * W2[8]  + hw * W2[12]) * di;
    r.y = (hx * W2[1] + hy * W2[5] + hz * W2[9]  + hw * W2[13]) * di;
    r.z = (hx * W2[2] + hy * W2[6] + hz * W2[10] + hw * W2[14]) * di;
    r.w = (hx * W2[3] + hy * W2[7] + hz * W2[11] + hw * W2[15]) * di;
    g_xw[i]  = r;
    g_agg[i] = r;
}

// Layer-2 edge pass: 4-wide. agg[dst] += xw[src].
__global__ void k_edge4(const int* __restrict__ e) {
    int t = blockIdx.x * blockDim.x + threadIdx.x;
    if (8 * t >= N_EDGES) return;
    LOAD_IDX8(e)
    float4 v0 = g_xw[s0.x];
    float4 v1 = g_xw[s0.y];
    float4 v2 = g_xw[s0.z];
    float4 v3 = g_xw[s0.w];
    float4 v4 = g_xw[s1.x];
    float4 v5 = g_xw[s1.y];
    float4 v6 = g_xw[s1.z];
    float4 v7 = g_xw[s1.w];
    red_add_f4(&g_agg[d0.x], v0);
    red_add_f4(&g_agg[d0.y], v1);
    red_add_f4(&g_agg[d0.z], v2);
    red_add_f4(&g_agg[d0.w], v3);
    red_add_f4(&g_agg[d1.x], v4);
    red_add_f4(&g_agg[d1.y], v5);
    red_add_f4(&g_agg[d1.z], v6);
    red_add_f4(&g_agg[d1.w], v7);
}

// Layer-3 node stage: h = tanh(agg*di + b2); xws3 = (h@W3)*di (2-wide);
// out initialized with self term (out is the layer-3 accumulator).
__global__ void k_node3(const float* __restrict__ W3, const float* __restrict__ b2,
                        float2* __restrict__ out) {
    int i = blockIdx.x * blockDim.x + threadIdx.x;
    if (i >= N_NODES) return;
    float di = g_dinv[i];
    float4 a = g_agg[i];
    float hx = tanhf(a.x * di + b2[0]);
    float hy = tanhf(a.y * di + b2[1]);
    float hz = tanhf(a.z * di + b2[2]);
    float hw = tanhf(a.w * di + b2[3]);
    float2 r;
    r.x = (hx * W3[0] + hy * W3[2] + hz * W3[4] + hw * W3[6]) * di;
    r.y = (hx * W3[1] + hy * W3[3] + hz * W3[5] + hw * W3[7]) * di;
    g_xw2[i] = r;
    out[i]   = r;
}

// Layer-3 edge pass: 2-wide, accumulating straight into d_out.
__global__ void k_edge2(const int* __restrict__ e, float2* __restrict__ out) {
    int t = blockIdx.x * blockDim.x + threadIdx.x;
    if (8 * t >= N_EDGES) return;
    LOAD_IDX8(e)
    float2 v0 = g_xw2[s0.x];
    float2 v1 = g_xw2[s0.y];
    float2 v2 = g_xw2[s0.z];
    float2 v3 = g_xw2[s0.w];
    float2 v4 = g_xw2[s1.x];
    float2 v5 = g_xw2[s1.y];
    float2 v6 = g_xw2[s1.z];
    float2 v7 = g_xw2[s1.w];
    red_add_f2(&out[d0.x], v0);
    red_add_f2(&out[d0.y], v1);
    red_add_f2(&out[d0.z], v2);
    red_add_f2(&out[d0.w], v3);
    red_add_f2(&out[d1.x], v4);
    red_add_f2(&out[d1.y], v5);
    red_add_f2(&out[d1.z], v6);
    red_add_f2(&out[d1.w], v7);
}

// Final scale + bias: out_i = agg_i * dinv_i + b3 (no tanh on last layer).
__global__ void k_finalize(float2* __restrict__ out, const float* __restrict__ b3) {
    int i = blockIdx.x * blockDim.x + threadIdx.x;
    if (i >= N_NODES) return;
    float di = g_dinv[i];
    float2 a = out[i];
    a.x = a.x * di + b3[0];
    a.y = a.y * di + b3[1];
    out[i] = a;
}

// ---------------- launch ----------------
extern "C" void kernel_launch(void* const* d_in, const int* in_sizes, int n_in,
                              void* d_out, int out_size) {
    const float* x  = (const float*)d_in[0];
    const int*   e  = (const int*)d_in[1];
    const float* W1 = (const float*)d_in[2];
    const float* b1 = (const float*)d_in[3];
    const float* W2 = (const float*)d_in[4];
    const float* b2 = (const float*)d_in[5];
    const float* W3 = (const float*)d_in[6];
    const float* b3 = (const float*)d_in[7];
    float2* out = (float2*)d_out;

    const int TB = 256;
    const int gNode  = (N_NODES + TB - 1) / TB;
    const int gEdge4 = (N_EDGES / 4 + TB - 1) / TB;
    const int gEdge8 = (N_EDGES / 8 + TB - 1) / TB;

    k_detect<<<1, 256>>>(e);
    k_zero_deg<<<gNode, TB>>>();
    k_prep_edges<<<gEdge4, TB>>>(e);

    k_node1<<<gNode, TB>>>(x);
    k_edge1<<<gEdge8, TB>>>(e);

    k_node2<<<gNode, TB>>>(W1, b1, W2);
    k_edge4<<<gEdge8, TB>>>(e);

    k_node3<<<gNode, TB>>>(W3, b2, out);
    k_edge2<<<gEdge8, TB>>>(e, out);
    k_finalize<<<gNode, TB>>>(out, b3);
}